// round 6
// baseline (speedup 1.0000x reference)
#include <cuda_runtime.h>
#include <cuda_bf16.h>
#include <math.h>
#include <stdint.h>

#define NN 256
#define NC 3
#define NPLANES 384

__device__ float g_S1[(size_t)NPLANES * NN * NN];   // T[p][k][w] fp32
__device__ __nv_bfloat16 g_D0[NN * NN];
__device__ __nv_bfloat16 g_D1[NN * NN];
__device__ __nv_bfloat16 g_D2[NN * NN];

// smem rows: 3 sub-tiles of 16 bf16 (32B each) padded to 112B stride
#define ROWB 112
#define TILEA (128 * ROWB)
#define TILEB_SZ (64 * ROWB)

// ---------------- helpers ----------------
__device__ __forceinline__ uint32_t smem_u32(const void* p) {
    uint32_t a;
    asm("{ .reg .u64 t; cvta.to.shared.u64 t, %1; cvt.u32.u64 %0, t; }" : "=r"(a) : "l"(p));
    return a;
}
__device__ __forceinline__ void ldsm_x4(uint32_t* r, uint32_t addr) {
    asm volatile("ldmatrix.sync.aligned.m8n8.x4.shared.b16 {%0,%1,%2,%3}, [%4];"
        : "=r"(r[0]), "=r"(r[1]), "=r"(r[2]), "=r"(r[3]) : "r"(addr));
}
// chained: d += a*b
__device__ __forceinline__ void mma_bf16(float* d, const uint32_t* a, const uint32_t* b) {
    asm volatile("mma.sync.aligned.m16n8k16.row.col.f32.bf16.bf16.f32 "
        "{%0,%1,%2,%3}, {%4,%5,%6,%7}, {%8,%9}, {%0,%1,%2,%3};"
        : "+f"(d[0]), "+f"(d[1]), "+f"(d[2]), "+f"(d[3])
        : "r"(a[0]), "r"(a[1]), "r"(a[2]), "r"(a[3]), "r"(b[0]), "r"(b[1]));
}
// fresh: d = a*b (C = 0)
__device__ __forceinline__ void mma_bf16_z(float* d, const uint32_t* a, const uint32_t* b) {
    asm volatile("mma.sync.aligned.m16n8k16.row.col.f32.bf16.bf16.f32 "
        "{%0,%1,%2,%3}, {%4,%5,%6,%7}, {%8,%9}, {%10,%10,%10,%10};"
        : "=f"(d[0]), "=f"(d[1]), "=f"(d[2]), "=f"(d[3])
        : "r"(a[0]), "r"(a[1]), "r"(a[2]), "r"(a[3]), "r"(b[0]), "r"(b[1]), "f"(0.0f));
}
__device__ __forceinline__ void split3(float v, uint16_t& s0, uint16_t& s1, uint16_t& s2) {
    __nv_bfloat16 b0 = __float2bfloat16(v);
    float r = v - __bfloat162float(b0);
    __nv_bfloat16 b1 = __float2bfloat16(r);
    float r2 = r - __bfloat162float(b1);
    __nv_bfloat16 b2 = __float2bfloat16(r2);
    s0 = __bfloat16_as_ushort(b0);
    s1 = __bfloat16_as_ushort(b1);
    s2 = __bfloat16_as_ushort(b2);
}
__device__ __forceinline__ uint32_t pack2u(uint16_t lo, uint16_t hi) {
    return (uint32_t)lo | ((uint32_t)hi << 16);
}

__global__ void compute_D_kernel() {
    int k = blockIdx.x;
    int h = threadIdx.x;
    float a = 3.14159274101257324f * ((float)h + 0.5f);
    a = a * (float)k;
    a = a * 0.00390625f;
    float v = (float)cos((double)a);
    v = v * 0.088388347f;
    if (k == 0) v = v * 0.70710677f;
    uint16_t s0, s1, s2;
    split3(v, s0, s1, s2);
    int i = k * NN + h;
    g_D0[i] = __ushort_as_bfloat16(s0);
    g_D1[i] = __ushort_as_bfloat16(s1);
    g_D2[i] = __ushort_as_bfloat16(s2);
}

__device__ __forceinline__ float log_precise(float x) {
    unsigned ix = __float_as_uint(x);
    int e = (int)(ix >> 23) - 126;
    float m = __uint_as_float((ix & 0x007FFFFFu) | 0x3F000000u);
    if (m < 0.70710678f) { m = m + m; e -= 1; }
    float f = m - 1.0f;
    float z = f * f;
    float p =            7.0376836292e-2f;
    p = fmaf(p, f, -1.1514610310e-1f);
    p = fmaf(p, f,  1.1676998740e-1f);
    p = fmaf(p, f, -1.2420140846e-1f);
    p = fmaf(p, f,  1.4249322787e-1f);
    p = fmaf(p, f, -1.6668057665e-1f);
    p = fmaf(p, f,  2.0000714765e-1f);
    p = fmaf(p, f, -2.4999993993e-1f);
    p = fmaf(p, f,  3.3333331174e-1f);
    float y = f * z * p;
    float fe = (float)e;
    y = fmaf(fe, -2.12194440e-4f, y);
    y = fmaf(-0.5f, z, y);
    float r = f + y;
    r = fmaf(fe, 0.693359375f, r);
    return r;
}

// D splits tile -> smem
__device__ __forceinline__ void load_D_tile(uint8_t* sm, int row0, int col0,
                                            int tid, int nrows) {
    int row = tid >> 1, half = tid & 1;
    if (row < nrows) {
        size_t g = (size_t)(row0 + row) * NN + col0 + half * 8;
        uint8_t* dst = sm + row * ROWB + half * 16;
        *(uint4*)(dst +  0) = *(const uint4*)(g_D0 + g);
        *(uint4*)(dst + 32) = *(const uint4*)(g_D1 + g);
        *(uint4*)(dst + 64) = *(const uint4*)(g_D2 + g);
    }
}

// one (A,B) block: 2x4 mmas; Z: first-write (C=0)
template <bool Z>
__device__ __forceinline__ void mma_blk(float acc[2][4][4], const uint32_t af[2][4],
                                        const uint32_t bf[2][4]) {
    #pragma unroll
    for (int mt = 0; mt < 2; mt++)
        #pragma unroll
        for (int nt = 0; nt < 4; nt++) {
            if (Z) mma_bf16_z(acc[mt][nt], af[mt], &bf[nt >> 1][(nt & 1) * 2]);
            else   mma_bf16  (acc[mt][nt], af[mt], &bf[nt >> 1][(nt & 1) * 2]);
        }
}

// per-chunk: 6 split-products into fresh acc (smalls first, big last),
// then master += acc with rn FADD.  12 ldsm.x4 total.
__device__ __forceinline__ void mma_chunk(const uint8_t* sA, const uint8_t* sB,
                                          float master[2][4][4], int lane,
                                          int warp_m, int warp_n) {
    uint32_t aBase = smem_u32(sA) + (warp_m * 32 + (lane & 15)) * ROWB + (lane >> 4) * 16;
    uint32_t bBase = smem_u32(sB) +
        (warp_n * 32 + ((lane >> 4) & 1) * 8 + (lane & 7)) * ROWB + ((lane >> 3) & 1) * 16;

    uint32_t b0f[2][4], b1f[2][4], b2f[2][4];
    #pragma unroll
    for (int h2 = 0; h2 < 2; h2++) {
        ldsm_x4(b0f[h2], bBase + h2 * 16 * ROWB);
        ldsm_x4(b1f[h2], bBase + h2 * 16 * ROWB + 32);
        ldsm_x4(b2f[h2], bBase + h2 * 16 * ROWB + 64);
    }

    float acc[2][4][4];
    uint32_t af[2][4];

    // A seg1: (1,0) fresh, (1,1)
    ldsm_x4(af[0], aBase + 32);
    ldsm_x4(af[1], aBase + 16 * ROWB + 32);
    mma_blk<true >(acc, af, b0f);
    mma_blk<false>(acc, af, b1f);
    // A seg2: (2,0)
    ldsm_x4(af[0], aBase + 64);
    ldsm_x4(af[1], aBase + 16 * ROWB + 64);
    mma_blk<false>(acc, af, b0f);
    // A seg0: (0,1), (0,2), (0,0) big last
    ldsm_x4(af[0], aBase);
    ldsm_x4(af[1], aBase + 16 * ROWB);
    mma_blk<false>(acc, af, b1f);
    mma_blk<false>(acc, af, b2f);
    mma_blk<false>(acc, af, b0f);

    #pragma unroll
    for (int mt = 0; mt < 2; mt++)
        #pragma unroll
        for (int nt = 0; nt < 4; nt++)
            #pragma unroll
            for (int e = 0; e < 4; e++)
                master[mt][nt][e] += acc[mt][nt][e];
}

#define ZERO_ACC(A)                                        \
    _Pragma("unroll") for (int i = 0; i < 2; i++)          \
    _Pragma("unroll") for (int j = 0; j < 4; j++)          \
    _Pragma("unroll") for (int e = 0; e < 4; e++) A[i][j][e] = 0.0f;

// ---------------------------------------------------------------------------
// GEMM1: T[k,w] = sum_h D[k,h] * x[b,h,w,c];  CTA tile 128(k) x 64(w)
// ---------------------------------------------------------------------------
__device__ __forceinline__ void fill_B1(uint8_t* sB, const float* xb, int h0,
                                        int tw, int tid) {
    #pragma unroll
    for (int l = 0; l < 2; l++) {
        int idx = tid + l * 256;
        int n = idx & 63, kp = idx >> 6;
        const float* px = xb + (size_t)(h0 + 2 * kp) * (NN * NC) + (size_t)(tw + n) * NC;
        float v0 = px[0], v1 = px[NN * NC];
        uint16_t a0, a1, a2, b0, b1, b2;
        split3(v0, a0, a1, a2);
        split3(v1, b0, b1, b2);
        uint8_t* dst = sB + n * ROWB + kp * 4;
        *(uint32_t*)(dst +  0) = pack2u(a0, b0);
        *(uint32_t*)(dst + 32) = pack2u(a1, b1);
        *(uint32_t*)(dst + 64) = pack2u(a2, b2);
    }
}

__global__ void __launch_bounds__(256, 2) dct_gemm1(const float* __restrict__ x) {
    __shared__ __align__(16) uint8_t sA[2][TILEA];
    __shared__ __align__(16) uint8_t sB[2][TILEB_SZ];
    int tid = threadIdx.x, wid = tid >> 5, lane = tid & 31;
    int warp_m = wid & 3, warp_n = wid >> 2;
    int p = blockIdx.y, b = p / 3, c = p - 3 * b;
    int tk = (blockIdx.x >> 2) * 128, tw = (blockIdx.x & 3) * 64;
    const float* xb = x + (size_t)b * NN * NN * NC + c;

    float master[2][4][4];
    ZERO_ACC(master);

    load_D_tile(sA[0], tk, 0, tid, 128);
    fill_B1(sB[0], xb, 0, tw, tid);
    __syncthreads();

    #pragma unroll 1
    for (int t = 0; t < 16; t++) {
        int buf = t & 1;
        if (t < 15) {
            load_D_tile(sA[buf ^ 1], tk, (t + 1) * 16, tid, 128);
            fill_B1(sB[buf ^ 1], xb, (t + 1) * 16, tw, tid);
        }
        mma_chunk(sA[buf], sB[buf], master, lane, warp_m, warp_n);
        __syncthreads();
    }

    float* S = g_S1 + (size_t)p * NN * NN;
    int r = lane >> 2, q = (lane & 3) * 2;
    #pragma unroll
    for (int mt = 0; mt < 2; mt++) {
        int m0 = tk + warp_m * 32 + mt * 16 + r;
        #pragma unroll
        for (int nt = 0; nt < 4; nt++) {
            int ncol = tw + warp_n * 32 + nt * 8 + q;
            *(float2*)(S + (size_t)m0 * NN + ncol) =
                make_float2(master[mt][nt][0], master[mt][nt][1]);
            *(float2*)(S + (size_t)(m0 + 8) * NN + ncol) =
                make_float2(master[mt][nt][2], master[mt][nt][3]);
        }
    }
}

// ---------------------------------------------------------------------------
// GEMM2: U[k,j] = sum_w T[k,w] * D[j,w]; fused log/normalize epilogue.
// ---------------------------------------------------------------------------
__device__ __forceinline__ void fill_A2(uint8_t* sA, const float* T, int tk,
                                        int w0, int tid) {
    #pragma unroll
    for (int l = 0; l < 4; l++) {
        int idx = tid + l * 256;
        int row = idx >> 3, kp = idx & 7;
        float2 v = *(const float2*)(T + (size_t)(tk + row) * NN + w0 + kp * 2);
        uint16_t a0, a1, a2, b0, b1, b2;
        split3(v.x, a0, a1, a2);
        split3(v.y, b0, b1, b2);
        uint8_t* dst = sA + row * ROWB + kp * 4;
        *(uint32_t*)(dst +  0) = pack2u(a0, b0);
        *(uint32_t*)(dst + 32) = pack2u(a1, b1);
        *(uint32_t*)(dst + 64) = pack2u(a2, b2);
    }
}

__global__ void __launch_bounds__(256, 2) dct_gemm2(const float* __restrict__ mean,
                                                    const float* __restrict__ stdv,
                                                    float* __restrict__ out) {
    __shared__ __align__(16) uint8_t sA[2][TILEA];
    __shared__ __align__(16) uint8_t sB[2][TILEB_SZ];
    int tid = threadIdx.x, wid = tid >> 5, lane = tid & 31;
    int warp_m = wid & 3, warp_n = wid >> 2;
    int p = blockIdx.y, b = p / 3, c = p - 3 * b;
    int tk = (blockIdx.x >> 2) * 128, tj = (blockIdx.x & 3) * 64;
    const float* T = g_S1 + (size_t)p * NN * NN;

    float master[2][4][4];
    ZERO_ACC(master);

    fill_A2(sA[0], T, tk, 0, tid);
    load_D_tile(sB[0], tj, 0, tid, 64);
    __syncthreads();

    #pragma unroll 1
    for (int t = 0; t < 16; t++) {
        int buf = t & 1;
        if (t < 15) {
            fill_A2(sA[buf ^ 1], T, tk, (t + 1) * 16, tid);
            load_D_tile(sB[buf ^ 1], tj, (t + 1) * 16, tid, 64);
        }
        mma_chunk(sA[buf], sB[buf], master, lane, warp_m, warp_n);
        __syncthreads();
    }

    int r = lane >> 2, q = (lane & 3) * 2;
    #pragma unroll
    for (int mt = 0; mt < 2; mt++) {
        #pragma unroll
        for (int nt = 0; nt < 4; nt++) {
            #pragma unroll
            for (int e = 0; e < 4; e++) {
                int krow = tk + warp_m * 32 + mt * 16 + r + (e >> 1) * 8;
                int j = tj + warp_n * 32 + nt * 8 + q + (e & 1);
                float y = master[mt][nt][e];
                float z = log_precise(fabsf(y) + 1e-13f);
                int mi = (krow * NN + j) * NC + c;
                out[((size_t)(b * NN + krow) * NN + j) * NC + c] =
                    (z - mean[mi]) / stdv[mi];
            }
        }
    }
}

// ---------------------------------------------------------------------------
extern "C" void kernel_launch(void* const* d_in, const int* in_sizes, int n_in,
                              void* d_out, int out_size) {
    const float* x    = (const float*)d_in[0];
    const float* mean = (const float*)d_in[1];
    const float* stdv = (const float*)d_in[2];
    float* out = (float*)d_out;

    compute_D_kernel<<<256, 256>>>();
    dct_gemm1<<<dim3(8, NPLANES), 256>>>(x);
    dct_gemm2<<<dim3(8, NPLANES), 256>>>(mean, stdv, out);
}

// round 7
// speedup vs baseline: 1.2182x; 1.2182x over previous
#include <cuda_runtime.h>
#include <cuda_fp16.h>
#include <math.h>
#include <stdint.h>

#define NN 256
#define NC 3
#define NPLANES 384

// T stored pre-split as two fp16 planes; D stored as fp16 splits
__device__ __half g_T0[(size_t)NPLANES * NN * NN];
__device__ __half g_T1[(size_t)NPLANES * NN * NN];
__device__ __half g_Dh0[NN * NN];
__device__ __half g_Dh1[NN * NN];

// smem rows: 2 segs x 16 fp16 (32B each) padded to 80B stride (5i mod 8 distinct -> conflict-free ldsm)
#define ROWB 80
#define TILEA (128 * ROWB)
#define TILEB_SZ (64 * ROWB)

// ---------------- helpers ----------------
__device__ __forceinline__ uint32_t smem_u32(const void* p) {
    uint32_t a;
    asm("{ .reg .u64 t; cvta.to.shared.u64 t, %1; cvt.u32.u64 %0, t; }" : "=r"(a) : "l"(p));
    return a;
}
__device__ __forceinline__ void ldsm_x4(uint32_t* r, uint32_t addr) {
    asm volatile("ldmatrix.sync.aligned.m8n8.x4.shared.b16 {%0,%1,%2,%3}, [%4];"
        : "=r"(r[0]), "=r"(r[1]), "=r"(r[2]), "=r"(r[3]) : "r"(addr));
}
// chained: d += a*b
__device__ __forceinline__ void mma_f16(float* d, const uint32_t* a, const uint32_t* b) {
    asm volatile("mma.sync.aligned.m16n8k16.row.col.f32.f16.f16.f32 "
        "{%0,%1,%2,%3}, {%4,%5,%6,%7}, {%8,%9}, {%0,%1,%2,%3};"
        : "+f"(d[0]), "+f"(d[1]), "+f"(d[2]), "+f"(d[3])
        : "r"(a[0]), "r"(a[1]), "r"(a[2]), "r"(a[3]), "r"(b[0]), "r"(b[1]));
}
// fresh: d = a*b (C = 0)
__device__ __forceinline__ void mma_f16_z(float* d, const uint32_t* a, const uint32_t* b) {
    asm volatile("mma.sync.aligned.m16n8k16.row.col.f32.f16.f16.f32 "
        "{%0,%1,%2,%3}, {%4,%5,%6,%7}, {%8,%9}, {%10,%10,%10,%10};"
        : "=f"(d[0]), "=f"(d[1]), "=f"(d[2]), "=f"(d[3])
        : "r"(a[0]), "r"(a[1]), "r"(a[2]), "r"(a[3]), "r"(b[0]), "r"(b[1]), "f"(0.0f));
}
__device__ __forceinline__ void split2(float v, uint16_t& s0, uint16_t& s1) {
    __half h0 = __float2half_rn(v);
    float r = v - __half2float(h0);
    __half h1 = __float2half_rn(r);
    s0 = __half_as_ushort(h0);
    s1 = __half_as_ushort(h1);
}
__device__ __forceinline__ uint32_t pack2u(uint16_t lo, uint16_t hi) {
    return (uint32_t)lo | ((uint32_t)hi << 16);
}

__global__ void compute_D_kernel() {
    int k = blockIdx.x;
    int h = threadIdx.x;
    float a = 3.14159274101257324f * ((float)h + 0.5f);
    a = a * (float)k;
    a = a * 0.00390625f;
    float v = (float)cos((double)a);
    v = v * 0.088388347f;
    if (k == 0) v = v * 0.70710677f;
    uint16_t s0, s1;
    split2(v, s0, s1);
    int i = k * NN + h;
    g_Dh0[i] = __ushort_as_half(s0);
    g_Dh1[i] = __ushort_as_half(s1);
}

__device__ __forceinline__ float log_precise(float x) {
    unsigned ix = __float_as_uint(x);
    int e = (int)(ix >> 23) - 126;
    float m = __uint_as_float((ix & 0x007FFFFFu) | 0x3F000000u);
    if (m < 0.70710678f) { m = m + m; e -= 1; }
    float f = m - 1.0f;
    float z = f * f;
    float p =            7.0376836292e-2f;
    p = fmaf(p, f, -1.1514610310e-1f);
    p = fmaf(p, f,  1.1676998740e-1f);
    p = fmaf(p, f, -1.2420140846e-1f);
    p = fmaf(p, f,  1.4249322787e-1f);
    p = fmaf(p, f, -1.6668057665e-1f);
    p = fmaf(p, f,  2.0000714765e-1f);
    p = fmaf(p, f, -2.4999993993e-1f);
    p = fmaf(p, f,  3.3333331174e-1f);
    float y = f * z * p;
    float fe = (float)e;
    y = fmaf(fe, -2.12194440e-4f, y);
    y = fmaf(-0.5f, z, y);
    float r = f + y;
    r = fmaf(fe, 0.693359375f, r);
    return r;
}

// copy pre-split fp16 tile (two planes) into smem: nrows rows from row0, 16 k-cols from col0
__device__ __forceinline__ void load_split_tile(uint8_t* sm, const __half* P0,
                                                const __half* P1, int row0, int col0,
                                                int tid, int nrows) {
    int row = tid >> 1, half = tid & 1;
    if (row < nrows) {
        size_t g = (size_t)(row0 + row) * NN + col0 + half * 8;
        uint8_t* dst = sm + row * ROWB + half * 16;
        *(uint4*)(dst +  0) = *(const uint4*)(P0 + g);
        *(uint4*)(dst + 32) = *(const uint4*)(P1 + g);
    }
}

// one (A,B) product block: 2x4 mmas
template <bool Z>
__device__ __forceinline__ void mma_blk(float acc[2][4][4], const uint32_t af[2][4],
                                        const uint32_t bf[2][4]) {
    #pragma unroll
    for (int mt = 0; mt < 2; mt++)
        #pragma unroll
        for (int nt = 0; nt < 4; nt++) {
            if (Z) mma_f16_z(acc[mt][nt], af[mt], &bf[nt >> 1][(nt & 1) * 2]);
            else   mma_f16  (acc[mt][nt], af[mt], &bf[nt >> 1][(nt & 1) * 2]);
        }
}

// per-chunk: 3 split-products into fresh acc (smalls first, big last),
// then master += acc (rn).  8 ldsm.x4, 24 mmas.
__device__ __forceinline__ void mma_chunk(const uint8_t* sA, const uint8_t* sB,
                                          float master[2][4][4], int lane,
                                          int warp_m, int warp_n) {
    uint32_t aBase = smem_u32(sA) + (warp_m * 32 + (lane & 15)) * ROWB + (lane >> 4) * 16;
    uint32_t bBase = smem_u32(sB) +
        (warp_n * 32 + ((lane >> 4) & 1) * 8 + (lane & 7)) * ROWB + ((lane >> 3) & 1) * 16;

    uint32_t a0f[2][4], a1f[2][4], b0f[2][4], b1f[2][4];
    #pragma unroll
    for (int mt = 0; mt < 2; mt++) {
        ldsm_x4(a0f[mt], aBase + mt * 16 * ROWB);
        ldsm_x4(a1f[mt], aBase + mt * 16 * ROWB + 32);
    }
    #pragma unroll
    for (int h2 = 0; h2 < 2; h2++) {
        ldsm_x4(b0f[h2], bBase + h2 * 16 * ROWB);
        ldsm_x4(b1f[h2], bBase + h2 * 16 * ROWB + 32);
    }

    float acc[2][4][4];
    mma_blk<true >(acc, a0f, b1f);   // big x small  (fresh)
    mma_blk<false>(acc, a1f, b0f);   // small x big  (chain, small magnitude)
    mma_blk<false>(acc, a0f, b0f);   // big x big    (last: one big-magnitude rounding)

    #pragma unroll
    for (int mt = 0; mt < 2; mt++)
        #pragma unroll
        for (int nt = 0; nt < 4; nt++)
            #pragma unroll
            for (int e = 0; e < 4; e++)
                master[mt][nt][e] += acc[mt][nt][e];
}

#define ZERO_ACC(A)                                        \
    _Pragma("unroll") for (int i = 0; i < 2; i++)          \
    _Pragma("unroll") for (int j = 0; j < 4; j++)          \
    _Pragma("unroll") for (int e = 0; e < 4; e++) A[i][j][e] = 0.0f;

// ---------------------------------------------------------------------------
// GEMM1: T[k,w] = sum_h D[k,h] * x[b,h,w,c];  CTA tile 128(k) x 64(w)
// ---------------------------------------------------------------------------
__device__ __forceinline__ void fill_B1(uint8_t* sB, const float* xb, int h0,
                                        int tw, int tid) {
    #pragma unroll
    for (int l = 0; l < 2; l++) {
        int idx = tid + l * 256;
        int n = idx & 63, kp = idx >> 6;   // kp 0..7 -> k = 2kp, 2kp+1
        const float* px = xb + (size_t)(h0 + 2 * kp) * (NN * NC) + (size_t)(tw + n) * NC;
        float v0 = px[0], v1 = px[NN * NC];
        uint16_t a0, a1, b0, b1;
        split2(v0, a0, a1);
        split2(v1, b0, b1);
        uint8_t* dst = sB + n * ROWB + kp * 4;
        *(uint32_t*)(dst +  0) = pack2u(a0, b0);
        *(uint32_t*)(dst + 32) = pack2u(a1, b1);
    }
}

__global__ void __launch_bounds__(256, 2) dct_gemm1(const float* __restrict__ x) {
    __shared__ __align__(16) uint8_t sA[2][TILEA];
    __shared__ __align__(16) uint8_t sB[2][TILEB_SZ];
    int tid = threadIdx.x, wid = tid >> 5, lane = tid & 31;
    int warp_m = wid & 3, warp_n = wid >> 2;
    int p = blockIdx.y, b = p / 3, c = p - 3 * b;
    int tk = (blockIdx.x >> 2) * 128, tw = (blockIdx.x & 3) * 64;
    const float* xb = x + (size_t)b * NN * NN * NC + c;

    float master[2][4][4];
    ZERO_ACC(master);

    load_split_tile(sA[0], g_Dh0, g_Dh1, tk, 0, tid, 128);
    fill_B1(sB[0], xb, 0, tw, tid);
    __syncthreads();

    #pragma unroll 1
    for (int t = 0; t < 16; t++) {
        int buf = t & 1;
        if (t < 15) {
            load_split_tile(sA[buf ^ 1], g_Dh0, g_Dh1, tk, (t + 1) * 16, tid, 128);
            fill_B1(sB[buf ^ 1], xb, (t + 1) * 16, tw, tid);
        }
        mma_chunk(sA[buf], sB[buf], master, lane, warp_m, warp_n);
        __syncthreads();
    }

    // epilogue: split T to fp16 planes (numerically identical to splitting in GEMM2)
    __half* T0 = g_T0 + (size_t)p * NN * NN;
    __half* T1 = g_T1 + (size_t)p * NN * NN;
    int r = lane >> 2, q = (lane & 3) * 2;
    #pragma unroll
    for (int mt = 0; mt < 2; mt++) {
        int m0 = tk + warp_m * 32 + mt * 16 + r;
        #pragma unroll
        for (int nt = 0; nt < 4; nt++) {
            int ncol = tw + warp_n * 32 + nt * 8 + q;
            #pragma unroll
            for (int half = 0; half < 2; half++) {
                int row = m0 + half * 8;
                float v0 = master[mt][nt][half * 2 + 0];
                float v1 = master[mt][nt][half * 2 + 1];
                uint16_t a0, a1, b0, b1;
                split2(v0, a0, a1);
                split2(v1, b0, b1);
                *(uint32_t*)(T0 + (size_t)row * NN + ncol) = pack2u(a0, b0);
                *(uint32_t*)(T1 + (size_t)row * NN + ncol) = pack2u(a1, b1);
            }
        }
    }
}

// ---------------------------------------------------------------------------
// GEMM2: U[k,j] = sum_w T[k,w] * D[j,w]; fused log/normalize epilogue.
// CTA tile 128(k) x 64(j); A and B both pre-split fp16 -> pure copies.
// ---------------------------------------------------------------------------
__global__ void __launch_bounds__(256, 2) dct_gemm2(const float* __restrict__ mean,
                                                    const float* __restrict__ stdv,
                                                    float* __restrict__ out) {
    __shared__ __align__(16) uint8_t sA[2][TILEA];
    __shared__ __align__(16) uint8_t sB[2][TILEB_SZ];
    int tid = threadIdx.x, wid = tid >> 5, lane = tid & 31;
    int warp_m = wid & 3, warp_n = wid >> 2;
    int p = blockIdx.y, b = p / 3, c = p - 3 * b;
    int tk = (blockIdx.x >> 2) * 128, tj = (blockIdx.x & 3) * 64;
    const __half* T0 = g_T0 + (size_t)p * NN * NN;
    const __half* T1 = g_T1 + (size_t)p * NN * NN;

    float master[2][4][4];
    ZERO_ACC(master);

    load_split_tile(sA[0], T0, T1, tk, 0, tid, 128);
    load_split_tile(sB[0], g_Dh0, g_Dh1, tj, 0, tid, 64);
    __syncthreads();

    #pragma unroll 1
    for (int t = 0; t < 16; t++) {
        int buf = t & 1;
        if (t < 15) {
            load_split_tile(sA[buf ^ 1], T0, T1, tk, (t + 1) * 16, tid, 128);
            load_split_tile(sB[buf ^ 1], g_Dh0, g_Dh1, tj, (t + 1) * 16, tid, 64);
        }
        mma_chunk(sA[buf], sB[buf], master, lane, warp_m, warp_n);
        __syncthreads();
    }

    int r = lane >> 2, q = (lane & 3) * 2;
    #pragma unroll
    for (int mt = 0; mt < 2; mt++) {
        #pragma unroll
        for (int nt = 0; nt < 4; nt++) {
            #pragma unroll
            for (int e = 0; e < 4; e++) {
                int krow = tk + warp_m * 32 + mt * 16 + r + (e >> 1) * 8;
                int j = tj + warp_n * 32 + nt * 8 + q + (e & 1);
                float y = master[mt][nt][e];
                float z = log_precise(fabsf(y) + 1e-13f);
                int mi = (krow * NN + j) * NC + c;
                out[((size_t)(b * NN + krow) * NN + j) * NC + c] =
                    (z - mean[mi]) / stdv[mi];
            }
        }
    }
}

// ---------------------------------------------------------------------------
extern "C" void kernel_launch(void* const* d_in, const int* in_sizes, int n_in,
                              void* d_out, int out_size) {
    const float* x    = (const float*)d_in[0];
    const float* mean = (const float*)d_in[1];
    const float* stdv = (const float*)d_in[2];
    float* out = (float*)d_out;

    compute_D_kernel<<<256, 256>>>();
    dct_gemm1<<<dim3(8, NPLANES), 256>>>(x);
    dct_gemm2<<<dim3(8, NPLANES), 256>>>(mean, stdv, out);
}

// round 8
// speedup vs baseline: 1.3231x; 1.0861x over previous
#include <cuda_runtime.h>
#include <cuda_fp16.h>
#include <math.h>
#include <stdint.h>

#define NN 256
#define NC 3
#define NPLANES 384

// T stored pre-split as two fp16 planes; D stored as fp16 splits
__device__ __half g_T0[(size_t)NPLANES * NN * NN];
__device__ __half g_T1[(size_t)NPLANES * NN * NN];
__device__ __half g_Dh0[NN * NN];
__device__ __half g_Dh1[NN * NN];

// smem rows: 2 segs x 16 fp16 (32B each) padded to 80B stride
#define ROWB 80
#define TILEA (128 * ROWB)
#define TILEB_SZ (64 * ROWB)

// ---------------- helpers ----------------
__device__ __forceinline__ uint32_t smem_u32(const void* p) {
    uint32_t a;
    asm("{ .reg .u64 t; cvta.to.shared.u64 t, %1; cvt.u32.u64 %0, t; }" : "=r"(a) : "l"(p));
    return a;
}
__device__ __forceinline__ void ldsm_x4(uint32_t* r, uint32_t addr) {
    asm volatile("ldmatrix.sync.aligned.m8n8.x4.shared.b16 {%0,%1,%2,%3}, [%4];"
        : "=r"(r[0]), "=r"(r[1]), "=r"(r[2]), "=r"(r[3]) : "r"(addr));
}
__device__ __forceinline__ void mma_f16(float* d, const uint32_t* a, const uint32_t* b) {
    asm volatile("mma.sync.aligned.m16n8k16.row.col.f32.f16.f16.f32 "
        "{%0,%1,%2,%3}, {%4,%5,%6,%7}, {%8,%9}, {%0,%1,%2,%3};"
        : "+f"(d[0]), "+f"(d[1]), "+f"(d[2]), "+f"(d[3])
        : "r"(a[0]), "r"(a[1]), "r"(a[2]), "r"(a[3]), "r"(b[0]), "r"(b[1]));
}
__device__ __forceinline__ void mma_f16_z(float* d, const uint32_t* a, const uint32_t* b) {
    asm volatile("mma.sync.aligned.m16n8k16.row.col.f32.f16.f16.f32 "
        "{%0,%1,%2,%3}, {%4,%5,%6,%7}, {%8,%9}, {%10,%10,%10,%10};"
        : "=f"(d[0]), "=f"(d[1]), "=f"(d[2]), "=f"(d[3])
        : "r"(a[0]), "r"(a[1]), "r"(a[2]), "r"(a[3]), "r"(b[0]), "r"(b[1]), "f"(0.0f));
}
__device__ __forceinline__ void split2(float v, uint16_t& s0, uint16_t& s1) {
    __half h0 = __float2half_rn(v);
    float r = v - __half2float(h0);
    __half h1 = __float2half_rn(r);
    s0 = __half_as_ushort(h0);
    s1 = __half_as_ushort(h1);
}
__device__ __forceinline__ uint32_t pack2u(uint16_t lo, uint16_t hi) {
    return (uint32_t)lo | ((uint32_t)hi << 16);
}

__global__ void compute_D_kernel() {
    int k = blockIdx.x;
    int h = threadIdx.x;
    float a = 3.14159274101257324f * ((float)h + 0.5f);
    a = a * (float)k;
    a = a * 0.00390625f;
    float v = (float)cos((double)a);
    v = v * 0.088388347f;
    if (k == 0) v = v * 0.70710677f;
    uint16_t s0, s1;
    split2(v, s0, s1);
    int i = k * NN + h;
    g_Dh0[i] = __ushort_as_half(s0);
    g_Dh1[i] = __ushort_as_half(s1);
}

__device__ __forceinline__ float log_precise(float x) {
    unsigned ix = __float_as_uint(x);
    int e = (int)(ix >> 23) - 126;
    float m = __uint_as_float((ix & 0x007FFFFFu) | 0x3F000000u);
    if (m < 0.70710678f) { m = m + m; e -= 1; }
    float f = m - 1.0f;
    float z = f * f;
    float p =            7.0376836292e-2f;
    p = fmaf(p, f, -1.1514610310e-1f);
    p = fmaf(p, f,  1.1676998740e-1f);
    p = fmaf(p, f, -1.2420140846e-1f);
    p = fmaf(p, f,  1.4249322787e-1f);
    p = fmaf(p, f, -1.6668057665e-1f);
    p = fmaf(p, f,  2.0000714765e-1f);
    p = fmaf(p, f, -2.4999993993e-1f);
    p = fmaf(p, f,  3.3333331174e-1f);
    float y = f * z * p;
    float fe = (float)e;
    y = fmaf(fe, -2.12194440e-4f, y);
    y = fmaf(-0.5f, z, y);
    float r = f + y;
    r = fmaf(fe, 0.693359375f, r);
    return r;
}

// ---- register-staged tile movers: gather (LDG->regs) and store (regs->STS) ----
struct TileRegs { uint4 u0, u1; };

__device__ __forceinline__ void gather_split_tile(TileRegs& tr, const __half* P0,
                                                  const __half* P1, int row0, int col0,
                                                  int tid, int nrows) {
    int row = tid >> 1, half = tid & 1;
    if (row < nrows) {
        size_t g = (size_t)(row0 + row) * NN + col0 + half * 8;
        tr.u0 = *(const uint4*)(P0 + g);
        tr.u1 = *(const uint4*)(P1 + g);
    }
}
__device__ __forceinline__ void store_split_tile(uint8_t* sm, const TileRegs& tr,
                                                 int tid, int nrows) {
    int row = tid >> 1, half = tid & 1;
    if (row < nrows) {
        uint8_t* dst = sm + row * ROWB + half * 16;
        *(uint4*)(dst +  0) = tr.u0;
        *(uint4*)(dst + 32) = tr.u1;
    }
}

struct B1Regs { float v[4]; };
__device__ __forceinline__ void gather_B1(B1Regs& br, const float* xb, int h0,
                                          int tw, int tid) {
    #pragma unroll
    for (int l = 0; l < 2; l++) {
        int idx = tid + l * 256;
        int n = idx & 63, kp = idx >> 6;
        const float* px = xb + (size_t)(h0 + 2 * kp) * (NN * NC) + (size_t)(tw + n) * NC;
        br.v[l * 2 + 0] = px[0];
        br.v[l * 2 + 1] = px[NN * NC];
    }
}
__device__ __forceinline__ void store_B1(uint8_t* sB, const B1Regs& br, int tid) {
    #pragma unroll
    for (int l = 0; l < 2; l++) {
        int idx = tid + l * 256;
        int n = idx & 63, kp = idx >> 6;
        uint16_t a0, a1, b0, b1;
        split2(br.v[l * 2 + 0], a0, a1);
        split2(br.v[l * 2 + 1], b0, b1);
        uint8_t* dst = sB + n * ROWB + kp * 4;
        *(uint32_t*)(dst +  0) = pack2u(a0, b0);
        *(uint32_t*)(dst + 32) = pack2u(a1, b1);
    }
}

// one (A,B) product block: 2x4 mmas
template <bool Z>
__device__ __forceinline__ void mma_blk(float acc[2][4][4], const uint32_t af[2][4],
                                        const uint32_t bf[2][4]) {
    #pragma unroll
    for (int mt = 0; mt < 2; mt++)
        #pragma unroll
        for (int nt = 0; nt < 4; nt++) {
            if (Z) mma_f16_z(acc[mt][nt], af[mt], &bf[nt >> 1][(nt & 1) * 2]);
            else   mma_f16  (acc[mt][nt], af[mt], &bf[nt >> 1][(nt & 1) * 2]);
        }
}

// per-chunk: 3 split-products into fresh acc (smalls first, big last),
// then master += acc (rn).
__device__ __forceinline__ void mma_chunk(const uint8_t* sA, const uint8_t* sB,
                                          float master[2][4][4], int lane,
                                          int warp_m, int warp_n) {
    uint32_t aBase = smem_u32(sA) + (warp_m * 32 + (lane & 15)) * ROWB + (lane >> 4) * 16;
    uint32_t bBase = smem_u32(sB) +
        (warp_n * 32 + ((lane >> 4) & 1) * 8 + (lane & 7)) * ROWB + ((lane >> 3) & 1) * 16;

    uint32_t a0f[2][4], a1f[2][4], b0f[2][4], b1f[2][4];
    #pragma unroll
    for (int mt = 0; mt < 2; mt++) {
        ldsm_x4(a0f[mt], aBase + mt * 16 * ROWB);
        ldsm_x4(a1f[mt], aBase + mt * 16 * ROWB + 32);
    }
    #pragma unroll
    for (int h2 = 0; h2 < 2; h2++) {
        ldsm_x4(b0f[h2], bBase + h2 * 16 * ROWB);
        ldsm_x4(b1f[h2], bBase + h2 * 16 * ROWB + 32);
    }

    float acc[2][4][4];
    mma_blk<true >(acc, a0f, b1f);   // big x small  (fresh)
    mma_blk<false>(acc, a1f, b0f);   // small x big
    mma_blk<false>(acc, a0f, b0f);   // big x big (last: one big rounding)

    #pragma unroll
    for (int mt = 0; mt < 2; mt++)
        #pragma unroll
        for (int nt = 0; nt < 4; nt++)
            #pragma unroll
            for (int e = 0; e < 4; e++)
                master[mt][nt][e] += acc[mt][nt][e];
}

#define ZERO_ACC(A)                                        \
    _Pragma("unroll") for (int i = 0; i < 2; i++)          \
    _Pragma("unroll") for (int j = 0; j < 4; j++)          \
    _Pragma("unroll") for (int e = 0; e < 4; e++) A[i][j][e] = 0.0f;

// ---------------------------------------------------------------------------
// GEMM1: T[k,w] = sum_h D[k,h] * x[b,h,w,c];  CTA tile 128(k) x 64(w)
// ---------------------------------------------------------------------------
__global__ void __launch_bounds__(256, 2) dct_gemm1(const float* __restrict__ x) {
    __shared__ __align__(16) uint8_t sA[2][TILEA];
    __shared__ __align__(16) uint8_t sB[2][TILEB_SZ];
    int tid = threadIdx.x, wid = tid >> 5, lane = tid & 31;
    int warp_m = wid & 3, warp_n = wid >> 2;
    int p = blockIdx.y, b = p / 3, c = p - 3 * b;
    int tk = (blockIdx.x >> 2) * 128, tw = (blockIdx.x & 3) * 64;
    const float* xb = x + (size_t)b * NN * NN * NC + c;

    float master[2][4][4];
    ZERO_ACC(master);

    {   // prologue: fill buf 0
        TileRegs ta; B1Regs rb;
        gather_split_tile(ta, g_Dh0, g_Dh1, tk, 0, tid, 128);
        gather_B1(rb, xb, 0, tw, tid);
        store_split_tile(sA[0], ta, tid, 128);
        store_B1(sB[0], rb, tid);
    }
    __syncthreads();

    #pragma unroll 1
    for (int t = 0; t < 16; t++) {
        int buf = t & 1;
        TileRegs ta; B1Regs rb;
        if (t < 15) {                          // LDG for t+1 issues FIRST
            gather_split_tile(ta, g_Dh0, g_Dh1, tk, (t + 1) * 16, tid, 128);
            gather_B1(rb, xb, (t + 1) * 16, tw, tid);
        }
        mma_chunk(sA[buf], sB[buf], master, lane, warp_m, warp_n);  // overlaps LDG
        if (t < 15) {                          // STS after compute
            store_split_tile(sA[buf ^ 1], ta, tid, 128);
            store_B1(sB[buf ^ 1], rb, tid);
        }
        __syncthreads();
    }

    // epilogue: split T to fp16 planes
    __half* T0 = g_T0 + (size_t)p * NN * NN;
    __half* T1 = g_T1 + (size_t)p * NN * NN;
    int r = lane >> 2, q = (lane & 3) * 2;
    #pragma unroll
    for (int mt = 0; mt < 2; mt++) {
        int m0 = tk + warp_m * 32 + mt * 16 + r;
        #pragma unroll
        for (int nt = 0; nt < 4; nt++) {
            int ncol = tw + warp_n * 32 + nt * 8 + q;
            #pragma unroll
            for (int half = 0; half < 2; half++) {
                int row = m0 + half * 8;
                uint16_t a0, a1, b0, b1;
                split2(master[mt][nt][half * 2 + 0], a0, a1);
                split2(master[mt][nt][half * 2 + 1], b0, b1);
                *(uint32_t*)(T0 + (size_t)row * NN + ncol) = pack2u(a0, b0);
                *(uint32_t*)(T1 + (size_t)row * NN + ncol) = pack2u(a1, b1);
            }
        }
    }
}

// ---------------------------------------------------------------------------
// GEMM2: U[k,j] = sum_w T[k,w] * D[j,w]; fused log/normalize epilogue.
// ---------------------------------------------------------------------------
__global__ void __launch_bounds__(256, 2) dct_gemm2(const float* __restrict__ mean,
                                                    const float* __restrict__ stdv,
                                                    float* __restrict__ out) {
    __shared__ __align__(16) uint8_t sA[2][TILEA];
    __shared__ __align__(16) uint8_t sB[2][TILEB_SZ];
    int tid = threadIdx.x, wid = tid >> 5, lane = tid & 31;
    int warp_m = wid & 3, warp_n = wid >> 2;
    int p = blockIdx.y, b = p / 3, c = p - 3 * b;
    int tk = (blockIdx.x >> 2) * 128, tj = (blockIdx.x & 3) * 64;
    const __half* T0 = g_T0 + (size_t)p * NN * NN;
    const __half* T1 = g_T1 + (size_t)p * NN * NN;

    float master[2][4][4];
    ZERO_ACC(master);

    {
        TileRegs ta, tb;
        gather_split_tile(ta, T0, T1, tk, 0, tid, 128);
        gather_split_tile(tb, g_Dh0, g_Dh1, tj, 0, tid, 64);
        store_split_tile(sA[0], ta, tid, 128);
        store_split_tile(sB[0], tb, tid, 64);
    }
    __syncthreads();

    #pragma unroll 1
    for (int t = 0; t < 16; t++) {
        int buf = t & 1;
        TileRegs ta, tb;
        if (t < 15) {
            gather_split_tile(ta, T0, T1, tk, (t + 1) * 16, tid, 128);
            gather_split_tile(tb, g_Dh0, g_Dh1, tj, (t + 1) * 16, tid, 64);
        }
        mma_chunk(sA[buf], sB[buf], master, lane, warp_m, warp_n);
        if (t < 15) {
            store_split_tile(sA[buf ^ 1], ta, tid, 128);
            store_split_tile(sB[buf ^ 1], tb, tid, 64);
        }
        __syncthreads();
    }

    int r = lane >> 2, q = (lane & 3) * 2;
    #pragma unroll
    for (int mt = 0; mt < 2; mt++) {
        #pragma unroll
        for (int nt = 0; nt < 4; nt++) {
            #pragma unroll
            for (int e = 0; e < 4; e++) {
                int krow = tk + warp_m * 32 + mt * 16 + r + (e >> 1) * 8;
                int j = tj + warp_n * 32 + nt * 8 + q + (e & 1);
                float y = master[mt][nt][e];
                float z = log_precise(fabsf(y) + 1e-13f);
                int mi = (krow * NN + j) * NC + c;
                out[((size_t)(b * NN + krow) * NN + j) * NC + c] =
                    (z - mean[mi]) / stdv[mi];
            }
        }
    }
}

// ---------------------------------------------------------------------------
extern "C" void kernel_launch(void* const* d_in, const int* in_sizes, int n_in,
                              void* d_out, int out_size) {
    const float* x    = (const float*)d_in[0];
    const float* mean = (const float*)d_in[1];
    const float* stdv = (const float*)d_in[2];
    float* out = (float*)d_out;

    compute_D_kernel<<<256, 256>>>();
    dct_gemm1<<<dim3(8, NPLANES), 256>>>(x);
    dct_gemm2<<<dim3(8, NPLANES), 256>>>(mean, stdv, out);
}

// round 9
// speedup vs baseline: 1.3761x; 1.0401x over previous
#include <cuda_runtime.h>
#include <cuda_fp16.h>
#include <math.h>
#include <stdint.h>

#define NN 256
#define NC 3
#define NPLANES 384

// T stored pre-split as two fp16 planes; D stored as fp16 splits
__device__ __half g_T0[(size_t)NPLANES * NN * NN];
__device__ __half g_T1[(size_t)NPLANES * NN * NN];
__device__ __half g_Dh0[NN * NN];
__device__ __half g_Dh1[NN * NN];

// smem rows: 128B = 8 x 16B units, XOR-swizzled: unit_phys = unit_log ^ (row & 7)
// unit_log = seg*4 + g, g = k>>3 (k in 0..31), seg in {0,1}
#define ROWB 128
#define TILEA (128 * ROWB)   // 16384
#define TILEB_SZ (64 * ROWB) //  8192

// ---------------- helpers ----------------
__device__ __forceinline__ uint32_t smem_u32(const void* p) {
    uint32_t a;
    asm("{ .reg .u64 t; cvta.to.shared.u64 t, %1; cvt.u32.u64 %0, t; }" : "=r"(a) : "l"(p));
    return a;
}
__device__ __forceinline__ void ldsm_x4(uint32_t* r, uint32_t addr) {
    asm volatile("ldmatrix.sync.aligned.m8n8.x4.shared.b16 {%0,%1,%2,%3}, [%4];"
        : "=r"(r[0]), "=r"(r[1]), "=r"(r[2]), "=r"(r[3]) : "r"(addr));
}
__device__ __forceinline__ void mma_f16(float* d, const uint32_t* a, const uint32_t* b) {
    asm volatile("mma.sync.aligned.m16n8k16.row.col.f32.f16.f16.f32 "
        "{%0,%1,%2,%3}, {%4,%5,%6,%7}, {%8,%9}, {%0,%1,%2,%3};"
        : "+f"(d[0]), "+f"(d[1]), "+f"(d[2]), "+f"(d[3])
        : "r"(a[0]), "r"(a[1]), "r"(a[2]), "r"(a[3]), "r"(b[0]), "r"(b[1]));
}
__device__ __forceinline__ void mma_f16_z(float* d, const uint32_t* a, const uint32_t* b) {
    asm volatile("mma.sync.aligned.m16n8k16.row.col.f32.f16.f16.f32 "
        "{%0,%1,%2,%3}, {%4,%5,%6,%7}, {%8,%9}, {%10,%10,%10,%10};"
        : "=f"(d[0]), "=f"(d[1]), "=f"(d[2]), "=f"(d[3])
        : "r"(a[0]), "r"(a[1]), "r"(a[2]), "r"(a[3]), "r"(b[0]), "r"(b[1]), "f"(0.0f));
}
__device__ __forceinline__ void split2(float v, uint16_t& s0, uint16_t& s1) {
    __half h0 = __float2half_rn(v);
    float r = v - __half2float(h0);
    __half h1 = __float2half_rn(r);
    s0 = __half_as_ushort(h0);
    s1 = __half_as_ushort(h1);
}
__device__ __forceinline__ uint32_t pack2u(uint16_t lo, uint16_t hi) {
    return (uint32_t)lo | ((uint32_t)hi << 16);
}

__global__ void compute_D_kernel() {
    int k = blockIdx.x;
    int h = threadIdx.x;
    float a = 3.14159274101257324f * ((float)h + 0.5f);
    a = a * (float)k;
    a = a * 0.00390625f;
    float v = (float)cos((double)a);
    v = v * 0.088388347f;
    if (k == 0) v = v * 0.70710677f;
    uint16_t s0, s1;
    split2(v, s0, s1);
    int i = k * NN + h;
    g_Dh0[i] = __ushort_as_half(s0);
    g_Dh1[i] = __ushort_as_half(s1);
}

__device__ __forceinline__ float log_precise(float x) {
    unsigned ix = __float_as_uint(x);
    int e = (int)(ix >> 23) - 126;
    float m = __uint_as_float((ix & 0x007FFFFFu) | 0x3F000000u);
    if (m < 0.70710678f) { m = m + m; e -= 1; }
    float f = m - 1.0f;
    float z = f * f;
    float p =            7.0376836292e-2f;
    p = fmaf(p, f, -1.1514610310e-1f);
    p = fmaf(p, f,  1.1676998740e-1f);
    p = fmaf(p, f, -1.2420140846e-1f);
    p = fmaf(p, f,  1.4249322787e-1f);
    p = fmaf(p, f, -1.6668057665e-1f);
    p = fmaf(p, f,  2.0000714765e-1f);
    p = fmaf(p, f, -2.4999993993e-1f);
    p = fmaf(p, f,  3.3333331174e-1f);
    float y = f * z * p;
    float fe = (float)e;
    y = fmaf(fe, -2.12194440e-4f, y);
    y = fmaf(-0.5f, z, y);
    float r = f + y;
    r = fmaf(fe, 0.693359375f, r);
    return r;
}

// ---- per-phase (16 k-cols) gather/store of pre-split fp16 planes ----
struct HalfRegs { uint4 q0, q1; };

__device__ __forceinline__ void gather_half(HalfRegs& hr, const __half* P0,
                                            const __half* P1, int row0, int col0,
                                            int tid, int nrows) {
    int row = tid >> 1, g = tid & 1;       // g: which 8-col group within the phase
    if (row < nrows) {
        size_t ga = (size_t)(row0 + row) * NN + col0 + g * 8;
        hr.q0 = *(const uint4*)(P0 + ga);
        hr.q1 = *(const uint4*)(P1 + ga);
    }
}
__device__ __forceinline__ void store_half(uint8_t* sm, const HalfRegs& hr, int ph,
                                           int tid, int nrows) {
    int row = tid >> 1, g = tid & 1;
    if (row < nrows) {
        int x = row & 7;
        int ul0 = ph * 2 + g;              // seg0 unit
        int ul1 = 4 + ph * 2 + g;          // seg1 unit
        uint8_t* base = sm + row * ROWB;
        *(uint4*)(base + ((ul0 ^ x) << 4)) = hr.q0;
        *(uint4*)(base + ((ul1 ^ x) << 4)) = hr.q1;
    }
}

// ---- GEMM1 B tile: gather fp32 x (stride-3) and split-store, per phase ----
struct B1Half { float v[4]; };
__device__ __forceinline__ void gather_B1h(B1Half& br, const float* xb, int h0k,
                                           int tw, int tid) {
    int n = tid & 63, ks = tid >> 6;       // ks 0..3 -> k = ks*4 + i
    const float* px = xb + (size_t)(h0k + ks * 4) * (NN * NC) + (size_t)(tw + n) * NC;
    #pragma unroll
    for (int i = 0; i < 4; i++) br.v[i] = px[(size_t)i * (NN * NC)];
}
__device__ __forceinline__ void store_B1h(uint8_t* sB, const B1Half& br, int ph, int tid) {
    int n = tid & 63, ks = tid >> 6;
    uint16_t s0[4], s1[4];
    #pragma unroll
    for (int i = 0; i < 4; i++) split2(br.v[i], s0[i], s1[i]);
    int x = n & 7;
    int ul0 = ph * 2 + (ks >> 1);
    int ul1 = 4 + ph * 2 + (ks >> 1);
    int sub = (ks & 1) * 8;
    uint8_t* base = sB + n * ROWB;
    *(uint2*)(base + ((ul0 ^ x) << 4) + sub) = make_uint2(pack2u(s0[0], s0[1]), pack2u(s0[2], s0[3]));
    *(uint2*)(base + ((ul1 ^ x) << 4) + sub) = make_uint2(pack2u(s1[0], s1[1]), pack2u(s1[2], s1[3]));
}

// one (A,B) product block: 2x4 mmas
template <bool Z>
__device__ __forceinline__ void mma_blk(float acc[2][4][4], const uint32_t af[2][4],
                                        const uint32_t bf[2][4]) {
    #pragma unroll
    for (int mt = 0; mt < 2; mt++)
        #pragma unroll
        for (int nt = 0; nt < 4; nt++) {
            if (Z) mma_f16_z(acc[mt][nt], af[mt], &bf[nt >> 1][(nt & 1) * 2]);
            else   mma_f16  (acc[mt][nt], af[mt], &bf[nt >> 1][(nt & 1) * 2]);
        }
}

// one 16-k sub-chunk: 8 ldsm (swizzled), 24 mmas (smalls fresh-first, big last),
// then master += acc (rn). Arithmetic identical to R8.
__device__ __forceinline__ void mma_sub(uint32_t sAb, uint32_t sBb,
                                        float master[2][4][4], int lane,
                                        int warp_m, int warp_n, int kc) {
    int rA = lane & 15, khA = lane >> 4, xA = rA & 7;
    int rB = ((lane >> 4) & 1) * 8 + (lane & 7), khB = (lane >> 3) & 1, xB = lane & 7;
    uint32_t aRow = sAb + (warp_m * 32 + rA) * ROWB;
    uint32_t bRow = sBb + (warp_n * 32 + rB) * ROWB;

    uint32_t a0f[2][4], a1f[2][4], b0f[2][4], b1f[2][4];
    #pragma unroll
    for (int mt = 0; mt < 2; mt++) {
        uint32_t rowOff = aRow + mt * 16 * ROWB;
        ldsm_x4(a0f[mt], rowOff + ((((kc * 2 + khA)    ) ^ xA) << 4));
        ldsm_x4(a1f[mt], rowOff + ((((kc * 2 + khA) + 4) ^ xA) << 4));
    }
    #pragma unroll
    for (int h2 = 0; h2 < 2; h2++) {
        uint32_t rowOff = bRow + h2 * 16 * ROWB;
        ldsm_x4(b0f[h2], rowOff + ((((kc * 2 + khB)    ) ^ xB) << 4));
        ldsm_x4(b1f[h2], rowOff + ((((kc * 2 + khB) + 4) ^ xB) << 4));
    }

    float acc[2][4][4];
    mma_blk<true >(acc, a0f, b1f);   // big x small (fresh)
    mma_blk<false>(acc, a1f, b0f);   // small x big
    mma_blk<false>(acc, a0f, b0f);   // big x big (last: one big rounding)

    #pragma unroll
    for (int mt = 0; mt < 2; mt++)
        #pragma unroll
        for (int nt = 0; nt < 4; nt++)
            #pragma unroll
            for (int e = 0; e < 4; e++)
                master[mt][nt][e] += acc[mt][nt][e];
}

#define ZERO_ACC(A)                                        \
    _Pragma("unroll") for (int i = 0; i < 2; i++)          \
    _Pragma("unroll") for (int j = 0; j < 4; j++)          \
    _Pragma("unroll") for (int e = 0; e < 4; e++) A[i][j][e] = 0.0f;

// ---------------------------------------------------------------------------
// GEMM1: T[k,w] = sum_h D[k,h] * x[b,h,w,c];  CTA tile 128(k) x 64(w), K-chunk 32
// ---------------------------------------------------------------------------
__global__ void __launch_bounds__(256, 2) dct_gemm1(const float* __restrict__ x) {
    __shared__ __align__(16) uint8_t sA[2][TILEA];
    __shared__ __align__(16) uint8_t sB[2][TILEB_SZ];
    int tid = threadIdx.x, wid = tid >> 5, lane = tid & 31;
    int warp_m = wid & 3, warp_n = wid >> 2;
    int p = blockIdx.y, b = p / 3, c = p - 3 * b;
    int tk = (blockIdx.x >> 2) * 128, tw = (blockIdx.x & 3) * 64;
    const float* xb = x + (size_t)b * NN * NN * NC + c;

    uint32_t sAb[2] = { smem_u32(sA[0]), smem_u32(sA[1]) };
    uint32_t sBb[2] = { smem_u32(sB[0]), smem_u32(sB[1]) };

    float master[2][4][4];
    ZERO_ACC(master);

    {   // prologue: both phases into buf 0
        #pragma unroll
        for (int ph = 0; ph < 2; ph++) {
            HalfRegs ha; B1Half hb;
            gather_half(ha, g_Dh0, g_Dh1, tk, ph * 16, tid, 128);
            gather_B1h(hb, xb, ph * 16, tw, tid);
            store_half(sA[0], ha, ph, tid, 128);
            store_B1h(sB[0], hb, ph, tid);
        }
    }
    __syncthreads();

    #pragma unroll 1
    for (int t = 0; t < 8; t++) {
        int buf = t & 1;
        int h0n = (t + 1) * 32;
        HalfRegs ha; B1Half hb;
        if (t < 7) {
            gather_half(ha, g_Dh0, g_Dh1, tk, h0n, tid, 128);
            gather_B1h(hb, xb, h0n, tw, tid);
        }
        mma_sub(sAb[buf], sBb[buf], master, lane, warp_m, warp_n, 0);
        if (t < 7) {
            store_half(sA[buf ^ 1], ha, 0, tid, 128);
            store_B1h(sB[buf ^ 1], hb, 0, tid);
            gather_half(ha, g_Dh0, g_Dh1, tk, h0n + 16, tid, 128);
            gather_B1h(hb, xb, h0n + 16, tw, tid);
        }
        mma_sub(sAb[buf], sBb[buf], master, lane, warp_m, warp_n, 1);
        if (t < 7) {
            store_half(sA[buf ^ 1], ha, 1, tid, 128);
            store_B1h(sB[buf ^ 1], hb, 1, tid);
        }
        __syncthreads();
    }

    // epilogue: split T to fp16 planes
    __half* T0 = g_T0 + (size_t)p * NN * NN;
    __half* T1 = g_T1 + (size_t)p * NN * NN;
    int r = lane >> 2, q = (lane & 3) * 2;
    #pragma unroll
    for (int mt = 0; mt < 2; mt++) {
        int m0 = tk + warp_m * 32 + mt * 16 + r;
        #pragma unroll
        for (int nt = 0; nt < 4; nt++) {
            int ncol = tw + warp_n * 32 + nt * 8 + q;
            #pragma unroll
            for (int hh = 0; hh < 2; hh++) {
                int row = m0 + hh * 8;
                uint16_t a0, a1, b0, b1;
                split2(master[mt][nt][hh * 2 + 0], a0, a1);
                split2(master[mt][nt][hh * 2 + 1], b0, b1);
                *(uint32_t*)(T0 + (size_t)row * NN + ncol) = pack2u(a0, b0);
                *(uint32_t*)(T1 + (size_t)row * NN + ncol) = pack2u(a1, b1);
            }
        }
    }
}

// ---------------------------------------------------------------------------
// GEMM2: U[k,j] = sum_w T[k,w] * D[j,w]; fused log/normalize epilogue.
// ---------------------------------------------------------------------------
__global__ void __launch_bounds__(256, 2) dct_gemm2(const float* __restrict__ mean,
                                                    const float* __restrict__ stdv,
                                                    float* __restrict__ out) {
    __shared__ __align__(16) uint8_t sA[2][TILEA];
    __shared__ __align__(16) uint8_t sB[2][TILEB_SZ];
    int tid = threadIdx.x, wid = tid >> 5, lane = tid & 31;
    int warp_m = wid & 3, warp_n = wid >> 2;
    int p = blockIdx.y, b = p / 3, c = p - 3 * b;
    int tk = (blockIdx.x >> 2) * 128, tj = (blockIdx.x & 3) * 64;
    const __half* T0 = g_T0 + (size_t)p * NN * NN;
    const __half* T1 = g_T1 + (size_t)p * NN * NN;

    uint32_t sAb[2] = { smem_u32(sA[0]), smem_u32(sA[1]) };
    uint32_t sBb[2] = { smem_u32(sB[0]), smem_u32(sB[1]) };

    float master[2][4][4];
    ZERO_ACC(master);

    {
        #pragma unroll
        for (int ph = 0; ph < 2; ph++) {
            HalfRegs ha, hb;
            gather_half(ha, T0, T1, tk, ph * 16, tid, 128);
            gather_half(hb, g_Dh0, g_Dh1, tj, ph * 16, tid, 64);
            store_half(sA[0], ha, ph, tid, 128);
            store_half(sB[0], hb, ph, tid, 64);
        }
    }
    __syncthreads();

    #pragma unroll 1
    for (int t = 0; t < 8; t++) {
        int buf = t & 1;
        int w0n = (t + 1) * 32;
        HalfRegs ha, hb;
        if (t < 7) {
            gather_half(ha, T0, T1, tk, w0n, tid, 128);
            gather_half(hb, g_Dh0, g_Dh1, tj, w0n, tid, 64);
        }
        mma_sub(sAb[buf], sBb[buf], master, lane, warp_m, warp_n, 0);
        if (t < 7) {
            store_half(sA[buf ^ 1], ha, 0, tid, 128);
            store_half(sB[buf ^ 1], hb, 0, tid, 64);
            gather_half(ha, T0, T1, tk, w0n + 16, tid, 128);
            gather_half(hb, g_Dh0, g_Dh1, tj, w0n + 16, tid, 64);
        }
        mma_sub(sAb[buf], sBb[buf], master, lane, warp_m, warp_n, 1);
        if (t < 7) {
            store_half(sA[buf ^ 1], ha, 1, tid, 128);
            store_half(sB[buf ^ 1], hb, 1, tid, 64);
        }
        __syncthreads();
    }

    int r = lane >> 2, q = (lane & 3) * 2;
    #pragma unroll
    for (int mt = 0; mt < 2; mt++) {
        #pragma unroll
        for (int nt = 0; nt < 4; nt++) {
            #pragma unroll
            for (int e = 0; e < 4; e++) {
                int krow = tk + warp_m * 32 + mt * 16 + r + (e >> 1) * 8;
                int j = tj + warp_n * 32 + nt * 8 + q + (e & 1);
                float y = master[mt][nt][e];
                float z = log_precise(fabsf(y) + 1e-13f);
                int mi = (krow * NN + j) * NC + c;
                out[((size_t)(b * NN + krow) * NN + j) * NC + c] =
                    (z - mean[mi]) / stdv[mi];
            }
        }
    }
}

// ---------------------------------------------------------------------------
extern "C" void kernel_launch(void* const* d_in, const int* in_sizes, int n_in,
                              void* d_out, int out_size) {
    const float* x    = (const float*)d_in[0];
    const float* mean = (const float*)d_in[1];
    const float* stdv = (const float*)d_in[2];
    float* out = (float*)d_out;

    compute_D_kernel<<<256, 256>>>();
    dct_gemm1<<<dim3(8, NPLANES), 256>>>(x);
    dct_gemm2<<<dim3(8, NPLANES), 256>>>(mean, stdv, out);
}

// round 10
// speedup vs baseline: 1.6089x; 1.1692x over previous
#include <cuda_runtime.h>
#include <cuda_fp16.h>
#include <math.h>
#include <stdint.h>

#define NN 256
#define NC 3
#define NPLANES 384

// T stored pre-split as two fp16 planes; D stored as fp16 splits
__device__ __half g_T0[(size_t)NPLANES * NN * NN];
__device__ __half g_T1[(size_t)NPLANES * NN * NN];
__device__ __half g_Dh0[NN * NN];
__device__ __half g_Dh1[NN * NN];

// smem rows: 128B = 8 x 16B units, XOR-swizzled: unit_phys = unit_log ^ (row & 7)
// unit_log = seg*4 + (ph*2+g), k-chunk of 32 = 2 phases x 16 cols
#define ROWB 128
#define TILEA (128 * ROWB)   // 16384
#define TILEB_SZ (64 * ROWB) //  8192

// ---------------- helpers ----------------
__device__ __forceinline__ uint32_t smem_u32(const void* p) {
    uint32_t a;
    asm("{ .reg .u64 t; cvta.to.shared.u64 t, %1; cvt.u32.u64 %0, t; }" : "=r"(a) : "l"(p));
    return a;
}
__device__ __forceinline__ void ldsm_x4(uint32_t* r, uint32_t addr) {
    asm volatile("ldmatrix.sync.aligned.m8n8.x4.shared.b16 {%0,%1,%2,%3}, [%4];"
        : "=r"(r[0]), "=r"(r[1]), "=r"(r[2]), "=r"(r[3]) : "r"(addr));
}
__device__ __forceinline__ void mma_f16(float* d, const uint32_t* a, const uint32_t* b) {
    asm volatile("mma.sync.aligned.m16n8k16.row.col.f32.f16.f16.f32 "
        "{%0,%1,%2,%3}, {%4,%5,%6,%7}, {%8,%9}, {%0,%1,%2,%3};"
        : "+f"(d[0]), "+f"(d[1]), "+f"(d[2]), "+f"(d[3])
        : "r"(a[0]), "r"(a[1]), "r"(a[2]), "r"(a[3]), "r"(b[0]), "r"(b[1]));
}
__device__ __forceinline__ void mma_f16_z(float* d, const uint32_t* a, const uint32_t* b) {
    asm volatile("mma.sync.aligned.m16n8k16.row.col.f32.f16.f16.f32 "
        "{%0,%1,%2,%3}, {%4,%5,%6,%7}, {%8,%9}, {%10,%10,%10,%10};"
        : "=f"(d[0]), "=f"(d[1]), "=f"(d[2]), "=f"(d[3])
        : "r"(a[0]), "r"(a[1]), "r"(a[2]), "r"(a[3]), "r"(b[0]), "r"(b[1]), "f"(0.0f));
}
__device__ __forceinline__ void split2(float v, uint16_t& s0, uint16_t& s1) {
    __half h0 = __float2half_rn(v);
    float r = v - __half2float(h0);
    __half h1 = __float2half_rn(r);
    s0 = __half_as_ushort(h0);
    s1 = __half_as_ushort(h1);
}
__device__ __forceinline__ uint32_t pack2u(uint16_t lo, uint16_t hi) {
    return (uint32_t)lo | ((uint32_t)hi << 16);
}

// ---- cp.async ----
__device__ __forceinline__ void cp16(uint32_t saddr, const void* gptr) {
    asm volatile("cp.async.cg.shared.global [%0], [%1], 16;" :: "r"(saddr), "l"(gptr));
}
#define CP_COMMIT() asm volatile("cp.async.commit_group;" ::: "memory")
#define CP_WAIT0()  asm volatile("cp.async.wait_group 0;" ::: "memory")

__global__ void compute_D_kernel() {
    int k = blockIdx.x;
    int h = threadIdx.x;
    float a = 3.14159274101257324f * ((float)h + 0.5f);
    a = a * (float)k;
    a = a * 0.00390625f;
    float v = (float)cos((double)a);
    v = v * 0.088388347f;
    if (k == 0) v = v * 0.70710677f;
    uint16_t s0, s1;
    split2(v, s0, s1);
    int i = k * NN + h;
    g_Dh0[i] = __ushort_as_half(s0);
    g_Dh1[i] = __ushort_as_half(s1);
}

__device__ __forceinline__ float log_precise(float x) {
    unsigned ix = __float_as_uint(x);
    int e = (int)(ix >> 23) - 126;
    float m = __uint_as_float((ix & 0x007FFFFFu) | 0x3F000000u);
    if (m < 0.70710678f) { m = m + m; e -= 1; }
    float f = m - 1.0f;
    float z = f * f;
    float p =            7.0376836292e-2f;
    p = fmaf(p, f, -1.1514610310e-1f);
    p = fmaf(p, f,  1.1676998740e-1f);
    p = fmaf(p, f, -1.2420140846e-1f);
    p = fmaf(p, f,  1.4249322787e-1f);
    p = fmaf(p, f, -1.6668057665e-1f);
    p = fmaf(p, f,  2.0000714765e-1f);
    p = fmaf(p, f, -2.4999993993e-1f);
    p = fmaf(p, f,  3.3333331174e-1f);
    float y = f * z * p;
    float fe = (float)e;
    y = fmaf(fe, -2.12194440e-4f, y);
    y = fmaf(-0.5f, z, y);
    float r = f + y;
    r = fmaf(fe, 0.693359375f, r);
    return r;
}

// async copy of pre-split fp16 planes, full K=32 chunk (both phases), swizzled
__device__ __forceinline__ void async_fill_split(uint32_t smb, const __half* P0,
                                                 const __half* P1, int row0, int k0,
                                                 int tid, int nrows) {
    int row = tid >> 1, g = tid & 1;
    if (row < nrows) {
        uint32_t base = smb + row * ROWB;
        int x = row & 7;
        #pragma unroll
        for (int ph = 0; ph < 2; ph++) {
            size_t ga = (size_t)(row0 + row) * NN + k0 + ph * 16 + g * 8;
            cp16(base + (((ph * 2 + g)     ^ x) << 4), P0 + ga);
            cp16(base + (((4 + ph * 2 + g) ^ x) << 4), P1 + ga);
        }
    }
}

// ---- GEMM1 B tile: gather fp32 x (stride-3) and split-store, per 16-col phase ----
struct B1Half { float v[4]; };
__device__ __forceinline__ void gather_B1h(B1Half& br, const float* xb, int h0k,
                                           int tw, int tid) {
    int n = tid & 63, ks = tid >> 6;
    const float* px = xb + (size_t)(h0k + ks * 4) * (NN * NC) + (size_t)(tw + n) * NC;
    #pragma unroll
    for (int i = 0; i < 4; i++) br.v[i] = px[(size_t)i * (NN * NC)];
}
__device__ __forceinline__ void store_B1h(uint8_t* sB, const B1Half& br, int ph, int tid) {
    int n = tid & 63, ks = tid >> 6;
    uint16_t s0[4], s1[4];
    #pragma unroll
    for (int i = 0; i < 4; i++) split2(br.v[i], s0[i], s1[i]);
    int x = n & 7;
    int ul0 = ph * 2 + (ks >> 1);
    int ul1 = 4 + ph * 2 + (ks >> 1);
    int sub = (ks & 1) * 8;
    uint8_t* base = sB + n * ROWB;
    *(uint2*)(base + ((ul0 ^ x) << 4) + sub) = make_uint2(pack2u(s0[0], s0[1]), pack2u(s0[2], s0[3]));
    *(uint2*)(base + ((ul1 ^ x) << 4) + sub) = make_uint2(pack2u(s1[0], s1[1]), pack2u(s1[2], s1[3]));
}

// one (A,B) product block: 2x4 mmas
template <bool Z>
__device__ __forceinline__ void mma_blk(float acc[2][4][4], const uint32_t af[2][4],
                                        const uint32_t bf[2][4]) {
    #pragma unroll
    for (int mt = 0; mt < 2; mt++)
        #pragma unroll
        for (int nt = 0; nt < 4; nt++) {
            if (Z) mma_f16_z(acc[mt][nt], af[mt], &bf[nt >> 1][(nt & 1) * 2]);
            else   mma_f16  (acc[mt][nt], af[mt], &bf[nt >> 1][(nt & 1) * 2]);
        }
}

// one 16-k sub-chunk: 8 ldsm (swizzled), 24 mmas (smalls fresh-first, big last),
// then master += acc (rn). Arithmetic identical to R9.
__device__ __forceinline__ void mma_sub(uint32_t sAb, uint32_t sBb,
                                        float master[2][4][4], int lane,
                                        int warp_m, int warp_n, int kc) {
    int rA = lane & 15, khA = lane >> 4, xA = rA & 7;
    int rB = ((lane >> 4) & 1) * 8 + (lane & 7), khB = (lane >> 3) & 1, xB = lane & 7;
    uint32_t aRow = sAb + (warp_m * 32 + rA) * ROWB;
    uint32_t bRow = sBb + (warp_n * 32 + rB) * ROWB;

    uint32_t a0f[2][4], a1f[2][4], b0f[2][4], b1f[2][4];
    #pragma unroll
    for (int mt = 0; mt < 2; mt++) {
        uint32_t rowOff = aRow + mt * 16 * ROWB;
        ldsm_x4(a0f[mt], rowOff + ((((kc * 2 + khA)    ) ^ xA) << 4));
        ldsm_x4(a1f[mt], rowOff + ((((kc * 2 + khA) + 4) ^ xA) << 4));
    }
    #pragma unroll
    for (int h2 = 0; h2 < 2; h2++) {
        uint32_t rowOff = bRow + h2 * 16 * ROWB;
        ldsm_x4(b0f[h2], rowOff + ((((kc * 2 + khB)    ) ^ xB) << 4));
        ldsm_x4(b1f[h2], rowOff + ((((kc * 2 + khB) + 4) ^ xB) << 4));
    }

    float acc[2][4][4];
    mma_blk<true >(acc, a0f, b1f);   // big x small (fresh)
    mma_blk<false>(acc, a1f, b0f);   // small x big
    mma_blk<false>(acc, a0f, b0f);   // big x big (last: one big rounding)

    #pragma unroll
    for (int mt = 0; mt < 2; mt++)
        #pragma unroll
        for (int nt = 0; nt < 4; nt++)
            #pragma unroll
            for (int e = 0; e < 4; e++)
                master[mt][nt][e] += acc[mt][nt][e];
}

#define ZERO_ACC(A)                                        \
    _Pragma("unroll") for (int i = 0; i < 2; i++)          \
    _Pragma("unroll") for (int j = 0; j < 4; j++)          \
    _Pragma("unroll") for (int e = 0; e < 4; e++) A[i][j][e] = 0.0f;

// ---------------------------------------------------------------------------
// GEMM1: T[k,w] = sum_h D[k,h] * x[b,h,w,c];  CTA tile 128(k) x 64(w), K-chunk 32
// A tile: cp.async; B tile: manual gather+split (register staged)
// ---------------------------------------------------------------------------
__global__ void __launch_bounds__(256, 2) dct_gemm1(const float* __restrict__ x) {
    __shared__ __align__(16) uint8_t sA[2][TILEA];
    __shared__ __align__(16) uint8_t sB[2][TILEB_SZ];
    int tid = threadIdx.x, wid = tid >> 5, lane = tid & 31;
    int warp_m = wid & 3, warp_n = wid >> 2;
    int p = blockIdx.y, b = p / 3, c = p - 3 * b;
    int tk = (blockIdx.x >> 2) * 128, tw = (blockIdx.x & 3) * 64;
    const float* xb = x + (size_t)b * NN * NN * NC + c;

    uint32_t sAb[2] = { smem_u32(sA[0]), smem_u32(sA[1]) };
    uint32_t sBb[2] = { smem_u32(sB[0]), smem_u32(sB[1]) };

    float master[2][4][4];
    ZERO_ACC(master);

    {   // prologue: fill buf 0
        async_fill_split(sAb[0], g_Dh0, g_Dh1, tk, 0, tid, 128);
        CP_COMMIT();
        B1Half hb;
        gather_B1h(hb, xb, 0, tw, tid);
        store_B1h(sB[0], hb, 0, tid);
        gather_B1h(hb, xb, 16, tw, tid);
        store_B1h(sB[0], hb, 1, tid);
        CP_WAIT0();
    }
    __syncthreads();

    #pragma unroll 1
    for (int t = 0; t < 8; t++) {
        int buf = t & 1;
        int h0n = (t + 1) * 32;
        B1Half hb;
        if (t < 7) {
            async_fill_split(sAb[buf ^ 1], g_Dh0, g_Dh1, tk, h0n, tid, 128);
            CP_COMMIT();
            gather_B1h(hb, xb, h0n, tw, tid);
        }
        mma_sub(sAb[buf], sBb[buf], master, lane, warp_m, warp_n, 0);
        if (t < 7) {
            store_B1h(sB[buf ^ 1], hb, 0, tid);
            gather_B1h(hb, xb, h0n + 16, tw, tid);
        }
        mma_sub(sAb[buf], sBb[buf], master, lane, warp_m, warp_n, 1);
        if (t < 7) {
            store_B1h(sB[buf ^ 1], hb, 1, tid);
            CP_WAIT0();
        }
        __syncthreads();
    }

    // epilogue: split T to fp16 planes
    __half* T0 = g_T0 + (size_t)p * NN * NN;
    __half* T1 = g_T1 + (size_t)p * NN * NN;
    int r = lane >> 2, q = (lane & 3) * 2;
    #pragma unroll
    for (int mt = 0; mt < 2; mt++) {
        int m0 = tk + warp_m * 32 + mt * 16 + r;
        #pragma unroll
        for (int nt = 0; nt < 4; nt++) {
            int ncol = tw + warp_n * 32 + nt * 8 + q;
            #pragma unroll
            for (int hh = 0; hh < 2; hh++) {
                int row = m0 + hh * 8;
                uint16_t a0, a1, b0, b1;
                split2(master[mt][nt][hh * 2 + 0], a0, a1);
                split2(master[mt][nt][hh * 2 + 1], b0, b1);
                *(uint32_t*)(T0 + (size_t)row * NN + ncol) = pack2u(a0, b0);
                *(uint32_t*)(T1 + (size_t)row * NN + ncol) = pack2u(a1, b1);
            }
        }
    }
}

// ---------------------------------------------------------------------------
// GEMM2: U[k,j] = sum_w T[k,w] * D[j,w]; all fills cp.async; fused epilogue.
// ---------------------------------------------------------------------------
__global__ void __launch_bounds__(256, 2) dct_gemm2(const float* __restrict__ mean,
                                                    const float* __restrict__ stdv,
                                                    float* __restrict__ out) {
    __shared__ __align__(16) uint8_t sA[2][TILEA];
    __shared__ __align__(16) uint8_t sB[2][TILEB_SZ];
    int tid = threadIdx.x, wid = tid >> 5, lane = tid & 31;
    int warp_m = wid & 3, warp_n = wid >> 2;
    int p = blockIdx.y, b = p / 3, c = p - 3 * b;
    int tk = (blockIdx.x >> 2) * 128, tj = (blockIdx.x & 3) * 64;
    const __half* T0 = g_T0 + (size_t)p * NN * NN;
    const __half* T1 = g_T1 + (size_t)p * NN * NN;

    uint32_t sAb[2] = { smem_u32(sA[0]), smem_u32(sA[1]) };
    uint32_t sBb[2] = { smem_u32(sB[0]), smem_u32(sB[1]) };

    float master[2][4][4];
    ZERO_ACC(master);

    async_fill_split(sAb[0], T0, T1, tk, 0, tid, 128);
    async_fill_split(sBb[0], g_Dh0, g_Dh1, tj, 0, tid, 64);
    CP_COMMIT();
    CP_WAIT0();
    __syncthreads();

    #pragma unroll 1
    for (int t = 0; t < 8; t++) {
        int buf = t & 1;
        int w0n = (t + 1) * 32;
        if (t < 7) {
            async_fill_split(sAb[buf ^ 1], T0, T1, tk, w0n, tid, 128);
            async_fill_split(sBb[buf ^ 1], g_Dh0, g_Dh1, tj, w0n, tid, 64);
            CP_COMMIT();
        }
        mma_sub(sAb[buf], sBb[buf], master, lane, warp_m, warp_n, 0);
        mma_sub(sAb[buf], sBb[buf], master, lane, warp_m, warp_n, 1);
        if (t < 7) CP_WAIT0();
        __syncthreads();
    }

    int r = lane >> 2, q = (lane & 3) * 2;
    #pragma unroll
    for (int mt = 0; mt < 2; mt++) {
        #pragma unroll
        for (int nt = 0; nt < 4; nt++) {
            #pragma unroll
            for (int e = 0; e < 4; e++) {
                int krow = tk + warp_m * 32 + mt * 16 + r + (e >> 1) * 8;
                int j = tj + warp_n * 32 + nt * 8 + q + (e & 1);
                float y = master[mt][nt][e];
                float z = log_precise(fabsf(y) + 1e-13f);
                int mi = (krow * NN + j) * NC + c;
                out[((size_t)(b * NN + krow) * NN + j) * NC + c] =
                    (z - mean[mi]) / stdv[mi];
            }
        }
    }
}

// ---------------------------------------------------------------------------
extern "C" void kernel_launch(void* const* d_in, const int* in_sizes, int n_in,
                              void* d_out, int out_size) {
    const float* x    = (const float*)d_in[0];
    const float* mean = (const float*)d_in[1];
    const float* stdv = (const float*)d_in[2];
    float* out = (float*)d_out;

    compute_D_kernel<<<256, 256>>>();
    dct_gemm1<<<dim3(8, NPLANES), 256>>>(x);
    dct_gemm2<<<dim3(8, NPLANES), 256>>>(mean, stdv, out);
}

// round 11
// speedup vs baseline: 1.6541x; 1.0281x over previous
#include <cuda_runtime.h>
#include <cuda_fp16.h>
#include <math.h>
#include <stdint.h>

#define NN 256
#define NC 3
#define NPLANES 384

// T stored pre-split as two fp16 planes; D stored as fp16 splits
__device__ __half g_T0[(size_t)NPLANES * NN * NN];
__device__ __half g_T1[(size_t)NPLANES * NN * NN];
__device__ __half g_Dh0[NN * NN];
__device__ __half g_Dh1[NN * NN];

// smem rows: 128B = 8 x 16B units, XOR-swizzled: unit_phys = unit_log ^ (row & 7)
#define ROWB 128
#define TILEA (128 * ROWB)   // 16384
#define TILEB_SZ (64 * ROWB) //  8192

// ---------------- helpers ----------------
__device__ __forceinline__ uint32_t smem_u32(const void* p) {
    uint32_t a;
    asm("{ .reg .u64 t; cvta.to.shared.u64 t, %1; cvt.u32.u64 %0, t; }" : "=r"(a) : "l"(p));
    return a;
}
__device__ __forceinline__ void ldsm_x4(uint32_t* r, uint32_t addr) {
    asm volatile("ldmatrix.sync.aligned.m8n8.x4.shared.b16 {%0,%1,%2,%3}, [%4];"
        : "=r"(r[0]), "=r"(r[1]), "=r"(r[2]), "=r"(r[3]) : "r"(addr));
}
__device__ __forceinline__ void mma_f16(float* d, const uint32_t* a, const uint32_t* b) {
    asm volatile("mma.sync.aligned.m16n8k16.row.col.f32.f16.f16.f32 "
        "{%0,%1,%2,%3}, {%4,%5,%6,%7}, {%8,%9}, {%0,%1,%2,%3};"
        : "+f"(d[0]), "+f"(d[1]), "+f"(d[2]), "+f"(d[3])
        : "r"(a[0]), "r"(a[1]), "r"(a[2]), "r"(a[3]), "r"(b[0]), "r"(b[1]));
}
__device__ __forceinline__ void mma_f16_z(float* d, const uint32_t* a, const uint32_t* b) {
    asm volatile("mma.sync.aligned.m16n8k16.row.col.f32.f16.f16.f32 "
        "{%0,%1,%2,%3}, {%4,%5,%6,%7}, {%8,%9}, {%10,%10,%10,%10};"
        : "=f"(d[0]), "=f"(d[1]), "=f"(d[2]), "=f"(d[3])
        : "r"(a[0]), "r"(a[1]), "r"(a[2]), "r"(a[3]), "r"(b[0]), "r"(b[1]), "f"(0.0f));
}
// packed master accumulate: m(f32x2) += {a1:a0}, rn per lane (bit-identical to 2 FADDs)
__device__ __forceinline__ void madd2(unsigned long long& m, float a0, float a1) {
    asm("{\n\t.reg .b64 aa;\n\tmov.b64 aa, {%1, %2};\n\tadd.rn.f32x2 %0, %0, aa;\n\t}"
        : "+l"(m) : "f"(a0), "f"(a1));
}
__device__ __forceinline__ float2 unpk2(unsigned long long m) {
    float2 r;
    asm("mov.b64 {%0, %1}, %2;" : "=f"(r.x), "=f"(r.y) : "l"(m));
    return r;
}
__device__ __forceinline__ void split2(float v, uint16_t& s0, uint16_t& s1) {
    __half h0 = __float2half_rn(v);
    float r = v - __half2float(h0);
    __half h1 = __float2half_rn(r);
    s0 = __half_as_ushort(h0);
    s1 = __half_as_ushort(h1);
}
// packed pair split: (v0,v1) -> h01={lo:h(v0),hi:h(v1)}, r01 residuals. Bit-identical
// to scalar split2 + pack2u (cvt.rn.f16x2.f32 rounds each lane rn).
__device__ __forceinline__ void split2x2(float v0, float v1, uint32_t& h01, uint32_t& r01) {
    asm("cvt.rn.f16x2.f32 %0, %1, %2;" : "=r"(h01) : "f"(v1), "f"(v0));
    __half2 hh = *reinterpret_cast<__half2*>(&h01);
    float f0 = __half2float(__low2half(hh));
    float f1 = __half2float(__high2half(hh));
    asm("cvt.rn.f16x2.f32 %0, %1, %2;" : "=r"(r01) : "f"(v1 - f1), "f"(v0 - f0));
}

// ---- cp.async ----
__device__ __forceinline__ void cp16(uint32_t saddr, const void* gptr) {
    asm volatile("cp.async.cg.shared.global [%0], [%1], 16;" :: "r"(saddr), "l"(gptr));
}
#define CP_COMMIT() asm volatile("cp.async.commit_group;" ::: "memory")
#define CP_WAIT0()  asm volatile("cp.async.wait_group 0;" ::: "memory")

__global__ void compute_D_kernel() {
    int k = blockIdx.x;
    int h = threadIdx.x;
    float a = 3.14159274101257324f * ((float)h + 0.5f);
    a = a * (float)k;
    a = a * 0.00390625f;
    float v = (float)cos((double)a);
    v = v * 0.088388347f;
    if (k == 0) v = v * 0.70710677f;
    uint16_t s0, s1;
    split2(v, s0, s1);
    int i = k * NN + h;
    g_Dh0[i] = __ushort_as_half(s0);
    g_Dh1[i] = __ushort_as_half(s1);
}

__device__ __forceinline__ float log_precise(float x) {
    unsigned ix = __float_as_uint(x);
    int e = (int)(ix >> 23) - 126;
    float m = __uint_as_float((ix & 0x007FFFFFu) | 0x3F000000u);
    if (m < 0.70710678f) { m = m + m; e -= 1; }
    float f = m - 1.0f;
    float z = f * f;
    float p =            7.0376836292e-2f;
    p = fmaf(p, f, -1.1514610310e-1f);
    p = fmaf(p, f,  1.1676998740e-1f);
    p = fmaf(p, f, -1.2420140846e-1f);
    p = fmaf(p, f,  1.4249322787e-1f);
    p = fmaf(p, f, -1.6668057665e-1f);
    p = fmaf(p, f,  2.0000714765e-1f);
    p = fmaf(p, f, -2.4999993993e-1f);
    p = fmaf(p, f,  3.3333331174e-1f);
    float y = f * z * p;
    float fe = (float)e;
    y = fmaf(fe, -2.12194440e-4f, y);
    y = fmaf(-0.5f, z, y);
    float r = f + y;
    r = fmaf(fe, 0.693359375f, r);
    return r;
}

// async copy of pre-split fp16 planes, full K=32 chunk, swizzled
__device__ __forceinline__ void async_fill_split(uint32_t smb, const __half* P0,
                                                 const __half* P1, int row0, int k0,
                                                 int tid, int nrows) {
    int row = tid >> 1, g = tid & 1;
    if (row < nrows) {
        uint32_t base = smb + row * ROWB;
        int x = row & 7;
        #pragma unroll
        for (int ph = 0; ph < 2; ph++) {
            size_t ga = (size_t)(row0 + row) * NN + k0 + ph * 16 + g * 8;
            cp16(base + (((ph * 2 + g)     ^ x) << 4), P0 + ga);
            cp16(base + (((4 + ph * 2 + g) ^ x) << 4), P1 + ga);
        }
    }
}

// ---- GEMM1 B tile: gather fp32 x (stride-3), packed split-store, per 16-col phase ----
struct B1Half { float v[4]; };
__device__ __forceinline__ void gather_B1h(B1Half& br, const float* xb, int h0k,
                                           int tw, int tid) {
    int n = tid & 63, ks = tid >> 6;
    const float* px = xb + (size_t)(h0k + ks * 4) * (NN * NC) + (size_t)(tw + n) * NC;
    #pragma unroll
    for (int i = 0; i < 4; i++) br.v[i] = px[(size_t)i * (NN * NC)];
}
__device__ __forceinline__ void store_B1h(uint8_t* sB, const B1Half& br, int ph, int tid) {
    int n = tid & 63, ks = tid >> 6;
    uint32_t h01, r01, h23, r23;
    split2x2(br.v[0], br.v[1], h01, r01);
    split2x2(br.v[2], br.v[3], h23, r23);
    int x = n & 7;
    int ul0 = ph * 2 + (ks >> 1);
    int ul1 = 4 + ph * 2 + (ks >> 1);
    int sub = (ks & 1) * 8;
    uint8_t* base = sB + n * ROWB;
    *(uint2*)(base + ((ul0 ^ x) << 4) + sub) = make_uint2(h01, h23);
    *(uint2*)(base + ((ul1 ^ x) << 4) + sub) = make_uint2(r01, r23);
}

// one (A,B) product block: 2x4 mmas
template <bool Z>
__device__ __forceinline__ void mma_blk(float acc[2][4][4], const uint32_t af[2][4],
                                        const uint32_t bf[2][4]) {
    #pragma unroll
    for (int mt = 0; mt < 2; mt++)
        #pragma unroll
        for (int nt = 0; nt < 4; nt++) {
            if (Z) mma_f16_z(acc[mt][nt], af[mt], &bf[nt >> 1][(nt & 1) * 2]);
            else   mma_f16  (acc[mt][nt], af[mt], &bf[nt >> 1][(nt & 1) * 2]);
        }
}

// one 16-k sub-chunk: 8 ldsm (swizzled), 24 mmas (smalls fresh-first, big last),
// then master += acc (packed rn). Arithmetic identical to R10.
// aRow/bRow precomputed (buffer base + warp/lane row offset).
__device__ __forceinline__ void mma_sub(uint32_t aRow, uint32_t bRow,
                                        unsigned long long master[2][4][2],
                                        int khA, int xA, int khB, int xB, int kc) {
    uint32_t a0f[2][4], a1f[2][4], b0f[2][4], b1f[2][4];
    #pragma unroll
    for (int mt = 0; mt < 2; mt++) {
        uint32_t rowOff = aRow + mt * 16 * ROWB;
        ldsm_x4(a0f[mt], rowOff + ((((kc * 2 + khA)    ) ^ xA) << 4));
        ldsm_x4(a1f[mt], rowOff + ((((kc * 2 + khA) + 4) ^ xA) << 4));
    }
    #pragma unroll
    for (int h2 = 0; h2 < 2; h2++) {
        uint32_t rowOff = bRow + h2 * 16 * ROWB;
        ldsm_x4(b0f[h2], rowOff + ((((kc * 2 + khB)    ) ^ xB) << 4));
        ldsm_x4(b1f[h2], rowOff + ((((kc * 2 + khB) + 4) ^ xB) << 4));
    }

    float acc[2][4][4];
    mma_blk<true >(acc, a0f, b1f);   // big x small (fresh)
    mma_blk<false>(acc, a1f, b0f);   // small x big
    mma_blk<false>(acc, a0f, b0f);   // big x big (last: one big rounding)

    #pragma unroll
    for (int mt = 0; mt < 2; mt++)
        #pragma unroll
        for (int nt = 0; nt < 4; nt++) {
            madd2(master[mt][nt][0], acc[mt][nt][0], acc[mt][nt][1]);
            madd2(master[mt][nt][1], acc[mt][nt][2], acc[mt][nt][3]);
        }
}

#define ZERO_ACC(A)                                        \
    _Pragma("unroll") for (int i = 0; i < 2; i++)          \
    _Pragma("unroll") for (int j = 0; j < 4; j++)          \
    _Pragma("unroll") for (int e = 0; e < 2; e++) A[i][j][e] = 0ull;

// ---------------------------------------------------------------------------
// GEMM1: T[k,w] = sum_h D[k,h] * x[b,h,w,c];  CTA tile 128(k) x 64(w), K-chunk 32
// ---------------------------------------------------------------------------
__global__ void __launch_bounds__(256, 2) dct_gemm1(const float* __restrict__ x) {
    __shared__ __align__(16) uint8_t sA[2][TILEA];
    __shared__ __align__(16) uint8_t sB[2][TILEB_SZ];
    int tid = threadIdx.x, wid = tid >> 5, lane = tid & 31;
    int warp_m = wid & 3, warp_n = wid >> 2;
    int p = blockIdx.y, b = p / 3, c = p - 3 * b;
    int tk = (blockIdx.x >> 2) * 128, tw = (blockIdx.x & 3) * 64;
    const float* xb = x + (size_t)b * NN * NN * NC + c;

    uint32_t sAb[2] = { smem_u32(sA[0]), smem_u32(sA[1]) };
    uint32_t sBb[2] = { smem_u32(sB[0]), smem_u32(sB[1]) };

    // hoisted ldsm lane addressing
    int rA = lane & 15, khA = lane >> 4, xA = rA & 7;
    int rB = ((lane >> 4) & 1) * 8 + (lane & 7), khB = (lane >> 3) & 1, xB = lane & 7;
    uint32_t aRowB[2] = { sAb[0] + (warp_m * 32 + rA) * ROWB, sAb[1] + (warp_m * 32 + rA) * ROWB };
    uint32_t bRowB[2] = { sBb[0] + (warp_n * 32 + rB) * ROWB, sBb[1] + (warp_n * 32 + rB) * ROWB };

    unsigned long long master[2][4][2];
    ZERO_ACC(master);

    {   // prologue: fill buf 0
        async_fill_split(sAb[0], g_Dh0, g_Dh1, tk, 0, tid, 128);
        CP_COMMIT();
        B1Half hb;
        gather_B1h(hb, xb, 0, tw, tid);
        store_B1h(sB[0], hb, 0, tid);
        gather_B1h(hb, xb, 16, tw, tid);
        store_B1h(sB[0], hb, 1, tid);
        CP_WAIT0();
    }
    __syncthreads();

    #pragma unroll 1
    for (int t = 0; t < 8; t++) {
        int buf = t & 1;
        int h0n = (t + 1) * 32;
        B1Half hb;
        if (t < 7) {
            async_fill_split(sAb[buf ^ 1], g_Dh0, g_Dh1, tk, h0n, tid, 128);
            CP_COMMIT();
            gather_B1h(hb, xb, h0n, tw, tid);
        }
        mma_sub(aRowB[buf], bRowB[buf], master, khA, xA, khB, xB, 0);
        if (t < 7) {
            store_B1h(sB[buf ^ 1], hb, 0, tid);
            gather_B1h(hb, xb, h0n + 16, tw, tid);
        }
        mma_sub(aRowB[buf], bRowB[buf], master, khA, xA, khB, xB, 1);
        if (t < 7) {
            store_B1h(sB[buf ^ 1], hb, 1, tid);
            CP_WAIT0();
        }
        __syncthreads();
    }

    // epilogue: split T to fp16 planes (packed cvts, bit-identical)
    __half* T0 = g_T0 + (size_t)p * NN * NN;
    __half* T1 = g_T1 + (size_t)p * NN * NN;
    int r = lane >> 2, q = (lane & 3) * 2;
    #pragma unroll
    for (int mt = 0; mt < 2; mt++) {
        int m0 = tk + warp_m * 32 + mt * 16 + r;
        #pragma unroll
        for (int nt = 0; nt < 4; nt++) {
            int ncol = tw + warp_n * 32 + nt * 8 + q;
            #pragma unroll
            for (int hh = 0; hh < 2; hh++) {
                int row = m0 + hh * 8;
                float2 v = unpk2(master[mt][nt][hh]);
                uint32_t t0p, t1p;
                split2x2(v.x, v.y, t0p, t1p);
                *(uint32_t*)(T0 + (size_t)row * NN + ncol) = t0p;
                *(uint32_t*)(T1 + (size_t)row * NN + ncol) = t1p;
            }
        }
    }
}

// ---------------------------------------------------------------------------
// GEMM2: U[k,j] = sum_w T[k,w] * D[j,w]; all fills cp.async; fused epilogue.
// ---------------------------------------------------------------------------
__global__ void __launch_bounds__(256, 2) dct_gemm2(const float* __restrict__ mean,
                                                    const float* __restrict__ stdv,
                                                    float* __restrict__ out) {
    __shared__ __align__(16) uint8_t sA[2][TILEA];
    __shared__ __align__(16) uint8_t sB[2][TILEB_SZ];
    int tid = threadIdx.x, wid = tid >> 5, lane = tid & 31;
    int warp_m = wid & 3, warp_n = wid >> 2;
    int p = blockIdx.y, b = p / 3, c = p - 3 * b;
    int tk = (blockIdx.x >> 2) * 128, tj = (blockIdx.x & 3) * 64;
    const __half* T0 = g_T0 + (size_t)p * NN * NN;
    const __half* T1 = g_T1 + (size_t)p * NN * NN;

    uint32_t sAb[2] = { smem_u32(sA[0]), smem_u32(sA[1]) };
    uint32_t sBb[2] = { smem_u32(sB[0]), smem_u32(sB[1]) };

    int rA = lane & 15, khA = lane >> 4, xA = rA & 7;
    int rB = ((lane >> 4) & 1) * 8 + (lane & 7), khB = (lane >> 3) & 1, xB = lane & 7;
    uint32_t aRowB[2] = { sAb[0] + (warp_m * 32 + rA) * ROWB, sAb[1] + (warp_m * 32 + rA) * ROWB };
    uint32_t bRowB[2] = { sBb[0] + (warp_n * 32 + rB) * ROWB, sBb[1] + (warp_n * 32 + rB) * ROWB };

    unsigned long long master[2][4][2];
    ZERO_ACC(master);

    async_fill_split(sAb[0], T0, T1, tk, 0, tid, 128);
    async_fill_split(sBb[0], g_Dh0, g_Dh1, tj, 0, tid, 64);
    CP_COMMIT();
    CP_WAIT0();
    __syncthreads();

    #pragma unroll 1
    for (int t = 0; t < 8; t++) {
        int buf = t & 1;
        int w0n = (t + 1) * 32;
        if (t < 7) {
            async_fill_split(sAb[buf ^ 1], T0, T1, tk, w0n, tid, 128);
            async_fill_split(sBb[buf ^ 1], g_Dh0, g_Dh1, tj, w0n, tid, 64);
            CP_COMMIT();
        }
        mma_sub(aRowB[buf], bRowB[buf], master, khA, xA, khB, xB, 0);
        mma_sub(aRowB[buf], bRowB[buf], master, khA, xA, khB, xB, 1);
        if (t < 7) CP_WAIT0();
        __syncthreads();
    }

    int r = lane >> 2, q = (lane & 3) * 2;
    #pragma unroll
    for (int mt = 0; mt < 2; mt++) {
        #pragma unroll
        for (int nt = 0; nt < 4; nt++) {
            #pragma unroll
            for (int hh = 0; hh < 2; hh++) {
                float2 v = unpk2(master[mt][nt][hh]);
                int krow = tk + warp_m * 32 + mt * 16 + r + hh * 8;
                int j0 = tj + warp_n * 32 + nt * 8 + q;
                float z0 = log_precise(fabsf(v.x) + 1e-13f);
                float z1 = log_precise(fabsf(v.y) + 1e-13f);
                int mi0 = (krow * NN + j0) * NC + c;
                int mi1 = mi0 + NC;
                size_t ob = ((size_t)(b * NN + krow) * NN + j0) * NC + c;
                out[ob]      = (z0 - mean[mi0]) / stdv[mi0];
                out[ob + NC] = (z1 - mean[mi1]) / stdv[mi1];
            }
        }
    }
}

// ---------------------------------------------------------------------------
extern "C" void kernel_launch(void* const* d_in, const int* in_sizes, int n_in,
                              void* d_out, int out_size) {
    const float* x    = (const float*)d_in[0];
    const float* mean = (const float*)d_in[1];
    const float* stdv = (const float*)d_in[2];
    float* out = (float*)d_out;

    compute_D_kernel<<<256, 256>>>();
    dct_gemm1<<<dim3(8, NPLANES), 256>>>(x);
    dct_gemm2<<<dim3(8, NPLANES), 256>>>(mean, stdv, out);
}